// round 15
// baseline (speedup 1.0000x reference)
#include <cuda_runtime.h>
#include <cuda_fp16.h>
#include <cstdint>

#define DIM 768
#define HEADS 12
#define HD 64
#define G 48
#define NTOK 2304
#define RANK 8
#define NKT 36      // 2304/64 k-tiles
#define QSCALE (0.125f * 1.44269504f)   // 1/sqrt(64) * log2(e), folded into q

// ---------------- scratch --------------------------------------------------
__device__ __align__(16) __half g_xh[NTOK*DIM];         // fp16 x, k-permuted
__device__ __align__(16) __half g_Wqkvh[3*DIM*DIM];     // fused [n][k-perm] fp16
__device__ __align__(16) __half g_Wph[DIM*DIM];         // [n][k-perm] fp16
__device__ __align__(16) __half g_qh[HEADS*NTOK*HD];    // fp16, xQSCALE, k-permuted
__device__ __align__(16) __half g_kh[HEADS*NTOK*HD];    // fp16, k-permuted
__device__ __align__(16) __half g_vh[HEADS*NTOK*HD];    // fp16 V^T [h][c][m'], m-permuted
__device__ __align__(16) __half g_rp16[2*(2*G-1)*HD];   // fp16 rp x8, k-permuted
__device__ __align__(16) float  g_relh[HEADS*NTOK*G];   // x log2e (via g_qh scale)
__device__ __align__(16) float  g_relw[HEADS*NTOK*G];
__device__ __align__(16) __half g_aoh[NTOK*DIM];        // fp16 attn out, k-permuted

// ---------------- helpers ---------------------------------------------------
__device__ __forceinline__ void mma16(float* d,
                                      uint32_t a0, uint32_t a1, uint32_t a2, uint32_t a3,
                                      uint32_t b0, uint32_t b1) {
    asm volatile("mma.sync.aligned.m16n8k16.row.col.f32.f16.f16.f32 "
                 "{%0,%1,%2,%3},{%4,%5,%6,%7},{%8,%9},{%0,%1,%2,%3};"
                 : "+f"(d[0]), "+f"(d[1]), "+f"(d[2]), "+f"(d[3])
                 : "r"(a0), "r"(a1), "r"(a2), "r"(a3), "r"(b0), "r"(b1));
}
__device__ __forceinline__ uint32_t packh2(float lo, float hi) {
    __half2 h = __floats2half2_rn(lo, hi);
    return *(uint32_t*)&h;
}
__device__ __forceinline__ uint32_t h2exp2(uint32_t x) {
    uint32_t r;
    asm("ex2.approx.f16x2 %0, %1;" : "=r"(r) : "r"(x));
    return r;
}
__device__ __forceinline__ void cpa16(uint32_t dst, const void* src) {
    asm volatile("cp.async.cg.shared.global [%0], [%1], 16;" :: "r"(dst), "l"(src));
}
#define CP_COMMIT() asm volatile("cp.async.commit_group;")
#define CP_WAIT(n)  asm volatile("cp.async.wait_group " #n ";")
#define ONES2 0x3C003C00u

// within-16 k-permutation for m16n8k16 frags: logical k -> phys 4*tt + 2*hi + lo
__device__ __forceinline__ int permk(int k) {
    int r = k & 15;
    return (k & ~15) + 4 * ((r & 7) >> 1) + 2 * (r >> 3) + (k & 1);
}

// ---------------- kernel 0: x -> fp16 k-permuted ----------------------------
__global__ __launch_bounds__(256) void round_x(const float* __restrict__ x) {
    int i = (blockIdx.x * 256 + threadIdx.x) * 4;
    float4 v = *(const float4*)(x + i);
    int p0 = permk(i);
    int p1 = permk(i + 2);
    *(__half2*)(g_xh + p0) = __floats2half2_rn(v.x, v.y);
    *(__half2*)(g_xh + p1) = __floats2half2_rn(v.z, v.w);
}

// ---------------- kernel 0b: rp tables -> fp16 x8 k-permuted ----------------
__global__ __launch_bounds__(256) void conv_rp(const float* __restrict__ rph,
                                               const float* __restrict__ rpw) {
    int id = blockIdx.x * 256 + threadIdx.x;
    if (id >= 2 * (2*G-1) * HD) return;
    int z = id / ((2*G-1) * HD);
    int rem = id - z * (2*G-1) * HD;
    int row = rem / HD, k = rem - row * HD;
    const float* src = z ? rpw : rph;
    g_rp16[z * (2*G-1) * HD + row * HD + permk(k)] =
        __float2half_rn(src[row * HD + k] * 8.f);
}

// ---------------- kernel 1: fuse LoRA + transpose -> fp16 k-permuted --------
__global__ __launch_bounds__(256) void fuse_wt(
    const float* __restrict__ Wq, const float* __restrict__ Aq, const float* __restrict__ Bq,
    const float* __restrict__ Wk, const float* __restrict__ Ak, const float* __restrict__ Bk,
    const float* __restrict__ Wv, const float* __restrict__ Av, const float* __restrict__ Bv,
    const float* __restrict__ Wp)
{
    __shared__ float tb[32][33];
    int z = blockIdx.z;
    const float *W, *A = nullptr, *B = nullptr;
    __half* O;
    if (z == 0)      { W = Wq; A = Aq; B = Bq; O = g_Wqkvh; }
    else if (z == 1) { W = Wk; A = Ak; B = Bk; O = g_Wqkvh + DIM*DIM; }
    else if (z == 2) { W = Wv; A = Av; B = Bv; O = g_Wqkvh + 2*DIM*DIM; }
    else             { W = Wp;                 O = g_Wph; }
    int kb = blockIdx.y * 32, nb = blockIdx.x * 32;
    int tx = threadIdx.x & 31, ty = threadIdx.x >> 5;
#pragma unroll
    for (int s = 0; s < 4; s++)
        tb[ty + 8 * s][tx] = W[(kb + ty + 8 * s) * DIM + nb + tx];
    __syncthreads();
#pragma unroll
    for (int s = 0; s < 4; s++) {
        int n = nb + ty + 8 * s;
        int k = kb + tx;
        float v = tb[tx][ty + 8 * s];
        if (z < 3) {
#pragma unroll
            for (int r = 0; r < RANK; r++)
                v += A[k * RANK + r] * B[r * DIM + n];
        }
        O[n * DIM + permk(k)] = __float2half_rn(v);
    }
}

// ---------------- fp16 GEMM core (templated warp grid) ---------------------
#define LDH 80
template<int WM, int WN, int NJ>
__device__ __forceinline__ void gemm16_body(const __half* __restrict__ Ain,
                                            const __half* __restrict__ Btn,
                                            float acc[2][NJ][4], __half* smh)
{
    const int MROWS = WM * 32;
    const int NROWS = WN * NJ * 8;
    const int BUFA = MROWS * LDH;
    const int BUFB = NROWS * LDH;
    int tid = threadIdx.x;
    int w = tid >> 5, l = tid & 31, g = l >> 2, t = l & 3;
    int wm = w / WN, wn = w % WN;
    __half* AS0 = smh;               __half* AS1 = AS0 + BUFA;
    __half* BS0 = AS1 + BUFA;        __half* BS1 = BS0 + BUFB;
    uint32_t as[2] = { (uint32_t)__cvta_generic_to_shared(AS0),
                       (uint32_t)__cvta_generic_to_shared(AS1) };
    uint32_t bs[2] = { (uint32_t)__cvta_generic_to_shared(BS0),
                       (uint32_t)__cvta_generic_to_shared(BS1) };

#pragma unroll
    for (int s = 0; s < MROWS / 32; s++) {
        int id = tid + s * 256;
        int r = id >> 3, ch = (id & 7) * 8;
        cpa16(as[0] + (r * LDH + ch) * 2, Ain + r * DIM + ch);
    }
#pragma unroll
    for (int s = 0; s < NROWS / 32; s++) {
        int id = tid + s * 256;
        int r = id >> 3, ch = (id & 7) * 8;
        cpa16(bs[0] + (r * LDH + ch) * 2, Btn + r * DIM + ch);
    }
    CP_COMMIT();

    for (int c = 0; c < 12; c++) {
        int buf = c & 1;
        if (c < 11) {
            int nb2 = buf ^ 1;
            int k0 = (c + 1) * 64;
#pragma unroll
            for (int s = 0; s < MROWS / 32; s++) {
                int id = tid + s * 256;
                int r = id >> 3, ch = (id & 7) * 8;
                cpa16(as[nb2] + (r * LDH + ch) * 2, Ain + r * DIM + k0 + ch);
            }
#pragma unroll
            for (int s = 0; s < NROWS / 32; s++) {
                int id = tid + s * 256;
                int r = id >> 3, ch = (id & 7) * 8;
                cpa16(bs[nb2] + (r * LDH + ch) * 2, Btn + r * DIM + k0 + ch);
            }
            CP_COMMIT();
            CP_WAIT(1);
        } else {
            CP_WAIT(0);
        }
        __syncthreads();
        const __half* As = buf ? AS1 : AS0;
        const __half* Bs = buf ? BS1 : BS0;
#pragma unroll
        for (int ks = 0; ks < 4; ks++) {
            int off = ks * 16 + 4 * t;
            uint32_t a[2][4];
#pragma unroll
            for (int i = 0; i < 2; i++) {
                int r = wm * 32 + i * 16;
                uint2 lo = *(const uint2*)&As[(r + g) * LDH + off];
                uint2 hi = *(const uint2*)&As[(r + g + 8) * LDH + off];
                a[i][0] = lo.x; a[i][1] = hi.x; a[i][2] = lo.y; a[i][3] = hi.y;
            }
#pragma unroll
            for (int j = 0; j < NJ; j++) {
                int n = wn * (NJ * 8) + j * 8;
                uint2 b = *(const uint2*)&Bs[(n + g) * LDH + off];
                mma16(acc[0][j], a[0][0], a[0][1], a[0][2], a[0][3], b.x, b.y);
                mma16(acc[1][j], a[1][0], a[1][1], a[1][2], a[1][3], b.x, b.y);
            }
        }
        __syncthreads();
    }
}

// ---------------- kernel 2: fused QKV GEMM (fp16, 128m x 128n) -------------
__global__ __launch_bounds__(256, 2) void gemm_qkvf(
    const float* __restrict__ bq, const float* __restrict__ bk, const float* __restrict__ bv)
{
    extern __shared__ __half smh[];
    int m0 = blockIdx.y * 128, n0 = blockIdx.x * 128;
    float acc[2][8][4];
#pragma unroll
    for (int i = 0; i < 2; i++)
#pragma unroll
        for (int j = 0; j < 8; j++)
#pragma unroll
            for (int e = 0; e < 4; e++) acc[i][j][e] = 0.f;
    gemm16_body<4, 2, 8>(g_xh + m0 * DIM, g_Wqkvh + n0 * DIM, acc, smh);

    int tid = threadIdx.x;
    int w = tid >> 5, l = tid & 31, g = l >> 2, t = l & 3;
    int wm = w >> 1, wn = w & 1;
#pragma unroll
    for (int i = 0; i < 2; i++) {
        int r0 = m0 + wm * 32 + i * 16 + g;
#pragma unroll
        for (int j = 0; j < 8; j++) {
            int cg = n0 + wn * 64 + j * 8 + t * 2;   // global col in [0, 3*DIM)
            int z = cg / DIM;
            int c = cg - z * DIM;
            const float* bias = (z == 0) ? bq : (z == 1) ? bk : bv;
            int h = c >> 6, cc = c & 63;
            float e0 = acc[i][j][0] + bias[c];
            float e1 = acc[i][j][1] + bias[c + 1];
            float e2 = acc[i][j][2] + bias[c];
            float e3 = acc[i][j][3] + bias[c + 1];
            if (z == 0) {
                int pcc = permk(cc);
                __half* qh = g_qh + h * (NTOK * HD);
                *(__half2*)&qh[r0 * HD + pcc]       = __floats2half2_rn(e0 * QSCALE, e1 * QSCALE);
                *(__half2*)&qh[(r0 + 8) * HD + pcc] = __floats2half2_rn(e2 * QSCALE, e3 * QSCALE);
            } else if (z == 1) {
                int pcc = permk(cc);
                __half* kh = g_kh + h * (NTOK * HD);
                *(__half2*)&kh[r0 * HD + pcc]       = __floats2half2_rn(e0, e1);
                *(__half2*)&kh[(r0 + 8) * HD + pcc] = __floats2half2_rn(e2, e3);
            } else {
                __half* vh = g_vh + h * (NTOK * HD);
                int pm0 = (r0 & ~15) + ((g >> 1) << 2) + (g & 1);
                int pm1 = pm0 + 2;
                vh[cc * NTOK + pm0]       = __float2half_rn(e0);
                vh[(cc + 1) * NTOK + pm0] = __float2half_rn(e1);
                vh[cc * NTOK + pm1]       = __float2half_rn(e2);
                vh[(cc + 1) * NTOK + pm1] = __float2half_rn(e3);
            }
        }
    }
}

// ---------------- kernel 5: output projection (fp16, 64m x 64n) -------------
__global__ __launch_bounds__(256, 3) void gemm_projf(
    const float* __restrict__ bp, float* __restrict__ out)
{
    extern __shared__ __half smh[];
    int m0 = blockIdx.y * 64, n0 = blockIdx.x * 64;
    float acc[2][2][4];
#pragma unroll
    for (int i = 0; i < 2; i++)
#pragma unroll
        for (int j = 0; j < 2; j++)
#pragma unroll
            for (int e = 0; e < 4; e++) acc[i][j][e] = 0.f;
    gemm16_body<2, 4, 2>(g_aoh + m0 * DIM, g_Wph + n0 * DIM, acc, smh);

    int tid = threadIdx.x;
    int w = tid >> 5, l = tid & 31, g = l >> 2, t = l & 3;
    int wm = w >> 2, wn = w & 3;
#pragma unroll
    for (int i = 0; i < 2; i++) {
        int r0 = m0 + wm * 32 + i * 16 + g;
#pragma unroll
        for (int j = 0; j < 2; j++) {
            int c = n0 + wn * 16 + j * 8 + t * 2;
            float2 v0 = make_float2(acc[i][j][0] + bp[c], acc[i][j][1] + bp[c + 1]);
            float2 v1 = make_float2(acc[i][j][2] + bp[c], acc[i][j][3] + bp[c + 1]);
            *(float2*)&out[r0 * DIM + c] = v0;
            *(float2*)&out[(r0 + 8) * DIM + c] = v1;
        }
    }
}

// ---------------- kernel 3: rel-pos tables, staging-free fp16 mma -----------
__global__ __launch_bounds__(192) void rel_mma_g()
{
    int head = blockIdx.x, p = blockIdx.y, z = blockIdx.z;
    int tid = threadIdx.x;
    int w = tid >> 5, l = tid & 31, g = l >> 2, t = l & 3;
    const __half* qhead = g_qh + head * (NTOK * HD);
    const __half* rpt = g_rp16 + z * (2*G-1) * HD;

    int brow = p + 47 - (w * 8 + g);
    uint2 bfr[4];
#pragma unroll
    for (int ks = 0; ks < 4; ks++)
        bfr[ks] = *(const uint2*)(rpt + brow * HD + 16 * ks + 4 * t);

    float acc[3][4];
#pragma unroll
    for (int i = 0; i < 3; i++)
#pragma unroll
        for (int e = 0; e < 4; e++) acc[i][e] = 0.f;

#pragma unroll
    for (int ks = 0; ks < 4; ks++) {
#pragma unroll
        for (int i = 0; i < 3; i++) {
            int rA = i * 16;
            int n0 = (z == 0) ? (p * G + rA + g)     : ((rA + g) * G + p);
            int n1 = (z == 0) ? (p * G + rA + g + 8) : ((rA + g + 8) * G + p);
            uint2 lo = *(const uint2*)(qhead + n0 * HD + 16 * ks + 4 * t);
            uint2 hi = *(const uint2*)(qhead + n1 * HD + 16 * ks + 4 * t);
            mma16(acc[i], lo.x, hi.x, lo.y, hi.y, bfr[ks].x, bfr[ks].y);
        }
    }

    float* dst = ((z == 0) ? g_relh : g_relw) + head * NTOK * G;
    int j = w * 8 + t * 2;
#pragma unroll
    for (int i = 0; i < 3; i++) {
        int r0 = i * 16 + g;
        int n0 = (z == 0) ? (p * G + r0)     : (r0 * G + p);
        int n1 = (z == 0) ? (p * G + r0 + 8) : ((r0 + 8) * G + p);
        *(float2*)&dst[n0 * G + j] = make_float2(acc[i][0], acc[i][1]);
        *(float2*)&dst[n1 * G + j] = make_float2(acc[i][2], acc[i][3]);
    }
}

// ---------------- kernel 4: fp16 flash, ex2.f16x2 + ones-mma l --------------
#define LKH 80
#define LVH 80
__global__ __launch_bounds__(256, 2) void flash8()
{
    extern __shared__ __half smf[];
    __half* Kb[2] = { smf,             smf + 64 * LKH };
    __half* Vb[2] = { smf + 2*64*LKH,  smf + 2*64*LKH + 64 * LVH };
    uint32_t kba[2] = { (uint32_t)__cvta_generic_to_shared(Kb[0]),
                        (uint32_t)__cvta_generic_to_shared(Kb[1]) };
    uint32_t vba[2] = { (uint32_t)__cvta_generic_to_shared(Vb[0]),
                        (uint32_t)__cvta_generic_to_shared(Vb[1]) };

    int tile = blockIdx.x, head = blockIdx.y;
    int tid = threadIdx.x, w = tid >> 5, l = tid & 31, g = l >> 2, t = l & 3;
    const __half* qhb = g_qh + head * (NTOK * HD) + tile * 128 * HD;
    const __half* khb = g_kh + head * (NTOK * HD);
    const __half* vhb = g_vh + head * (NTOK * HD);

    int pr = w * 16;
    uint32_t qa[4][4];
#pragma unroll
    for (int ks = 0; ks < 4; ks++) {
        uint2 lo = *(const uint2*)(qhb + (pr + g) * HD + 16 * ks + 4 * t);
        uint2 hi = *(const uint2*)(qhb + (pr + g + 8) * HD + 16 * ks + 4 * t);
        qa[ks][0] = lo.x; qa[ks][1] = hi.x; qa[ks][2] = lo.y; qa[ks][3] = hi.y;
    }

#pragma unroll
    for (int s = 0; s < 2; s++) {
        int id = tid + s * 256;
        int r = id >> 3, ch = (id & 7) * 8;
        cpa16(kba[0] + (r * LKH + ch) * 2, khb + r * HD + ch);
        cpa16(vba[0] + (r * LVH + ch) * 2, vhb + r * NTOK + ch);
    }
    CP_COMMIT();

    int rg0 = tile * 128 + pr + g;
    const float* rhb = g_relh + head * NTOK * G;
    const float* rwb = g_relw + head * NTOK * G;

    float o[8][4];
#pragma unroll
    for (int j = 0; j < 8; j++)
#pragma unroll
        for (int e = 0; e < 4; e++) o[j][e] = 0.f;
    float ol[4] = {0.f, 0.f, 0.f, 0.f};

    for (int kt = 0; kt < NKT; kt++) {
        CP_WAIT(0);
        __syncthreads();

        if (kt + 1 < NKT) {
            int nb = (kt + 1) & 1;
            const __half* ksrc = khb + (kt + 1) * 64 * HD;
            const __half* vsrc = vhb + (kt + 1) * 64;
#pragma unroll
            for (int s = 0; s < 2; s++) {
                int id = tid + s * 256;
                int r = id >> 3, ch = (id & 7) * 8;
                cpa16(kba[nb] + (r * LKH + ch) * 2, ksrc + r * HD + ch);
                cpa16(vba[nb] + (r * LVH + ch) * 2, vsrc + r * NTOK + ch);
            }
            CP_COMMIT();
        }

        const __half* Ks = Kb[kt & 1];
        const __half* Vt = Vb[kt & 1];

        float s4[8][4];
#pragma unroll
        for (int j = 0; j < 8; j++)
#pragma unroll
            for (int e = 0; e < 4; e++) s4[j][e] = 0.f;
#pragma unroll
        for (int ks = 0; ks < 4; ks++) {
#pragma unroll
            for (int j = 0; j < 8; j++) {
                uint2 b = *(const uint2*)&Ks[(j * 8 + g) * LKH + 16 * ks + 4 * t];
                mma16(s4[j], qa[ks][0], qa[ks][1], qa[ks][2], qa[ks][3], b.x, b.y);
            }
        }

        int colbase = kt * 64;
        int khA = colbase / G;
        int khB = (colbase + 63) / G;
        float rhA0 = rhb[rg0 * G + khA],       rhB0 = rhb[rg0 * G + khB];
        float rhA1 = rhb[(rg0 + 8) * G + khA], rhB1 = rhb[(rg0 + 8) * G + khB];
        uint32_t pa[8][2];
#pragma unroll
        for (int j = 0; j < 8; j++) {
            int c0 = colbase + j * 8 + t * 2;
            int kh0 = c0 / G, kw0 = c0 - kh0 * G;
            float rh0 = (kh0 == khA) ? rhA0 : rhB0;
            float rh1 = (kh0 == khA) ? rhA1 : rhB1;
            float2 w0 = *(const float2*)&rwb[rg0 * G + kw0];
            float2 w1 = *(const float2*)&rwb[(rg0 + 8) * G + kw0];
            pa[j][0] = h2exp2(packh2(s4[j][0] + rh0 + w0.x, s4[j][1] + rh0 + w0.y));
            pa[j][1] = h2exp2(packh2(s4[j][2] + rh1 + w1.x, s4[j][3] + rh1 + w1.y));
        }

#pragma unroll
        for (int ms = 0; ms < 4; ms++) {
            uint32_t a0 = pa[2*ms][0],   a1 = pa[2*ms][1];
            uint32_t a2 = pa[2*ms+1][0], a3 = pa[2*ms+1][1];
            mma16(ol, a0, a1, a2, a3, ONES2, ONES2);
#pragma unroll
            for (int j = 0; j < 8; j++) {
                uint2 b = *(const uint2*)&Vt[(j * 8 + g) * LVH + 16 * ms + 4 * t];
                mma16(o[j], a0, a1, a2, a3, b.x, b.y);
            }
        }
    }

    float inv0 = 1.f / ol[0], inv1 = 1.f / ol[2];

    int nq0 = tile * 128 + pr + g;
#pragma unroll
    for (int j = 0; j < 8; j++) {
        int c = head * HD + j * 8 + t * 2;
        int pc = permk(c);
        *(__half2*)&g_aoh[nq0 * DIM + pc]       = __floats2half2_rn(o[j][0] * inv0, o[j][1] * inv0);
        *(__half2*)&g_aoh[(nq0 + 8) * DIM + pc] = __floats2half2_rn(o[j][2] * inv1, o[j][3] * inv1);
    }
}

// ---------------- launch ----------------------------------------------------
extern "C" void kernel_launch(void* const* d_in, const int* in_sizes, int n_in,
                              void* d_out, int out_size)
{
    const float* x   = (const float*)d_in[0];
    const float* Wq  = (const float*)d_in[1];
    const float* bq  = (const float*)d_in[2];
    const float* Wk  = (const float*)d_in[3];
    const float* bk  = (const float*)d_in[4];
    const float* Wv  = (const float*)d_in[5];
    const float* bv  = (const float*)d_in[6];
    const float* Wp  = (const float*)d_in[7];
    const float* bp  = (const float*)d_in[8];
    const float* rph = (const float*)d_in[9];
    const float* rpw = (const float*)d_in[10];
    const float* Aq  = (const float*)d_in[11];
    const float* Bq  = (const float*)d_in[12];
    const float* Ak  = (const float*)d_in[13];
    const float* Bk  = (const float*)d_in[14];
    const float* Av  = (const float*)d_in[15];
    const float* Bv  = (const float*)d_in[16];
    float* out = (float*)d_out;

    const int qkv_smem   = 2 * (128 + 128) * LDH * (int)sizeof(__half);          // 81920
    const int proj_smem  = 2 * (64 + 64) * LDH * (int)sizeof(__half);            // 40960
    const int flash_smem = (2 * 64 * LKH + 2 * 64 * LVH) * (int)sizeof(__half);  // 40960
    cudaFuncSetAttribute(gemm_qkvf, cudaFuncAttributeMaxDynamicSharedMemorySize, qkv_smem);
    cudaFuncSetAttribute(gemm_projf, cudaFuncAttributeMaxDynamicSharedMemorySize, proj_smem);
    cudaFuncSetAttribute(flash8, cudaFuncAttributeMaxDynamicSharedMemorySize, flash_smem);

    round_x<<<NTOK * DIM / 1024, 256>>>(x);
    conv_rp<<<(2 * (2*G-1) * HD + 255) / 256, 256>>>(rph, rpw);
    fuse_wt<<<dim3(24, 24, 4), 256>>>(Wq, Aq, Bq, Wk, Ak, Bk, Wv, Av, Bv, Wp);
    gemm_qkvf<<<dim3(18, 18), 256, qkv_smem>>>(bq, bk, bv);
    rel_mma_g<<<dim3(HEADS, G, 2), 192>>>();
    flash8<<<dim3(NTOK / 128, HEADS), 256, flash_smem>>>();
    gemm_projf<<<dim3(12, 36), 256, proj_smem>>>(bp, out);
}

// round 16
// speedup vs baseline: 1.1621x; 1.1621x over previous
#include <cuda_runtime.h>
#include <cuda_fp16.h>
#include <cstdint>

#define DIM 768
#define HEADS 12
#define HD 64
#define G 48
#define NTOK 2304
#define RANK 8
#define NKT 36      // 2304/64 k-tiles
#define QSCALE (0.125f * 1.44269504f)   // 1/sqrt(64) * log2(e), folded into q

// ---------------- scratch --------------------------------------------------
__device__ __align__(16) __half g_xh[NTOK*DIM];         // fp16 x, k-permuted
__device__ __align__(16) __half g_Wqkvh[3*DIM*DIM];     // fused [n][k-perm] fp16
__device__ __align__(16) __half g_Wph[DIM*DIM];         // [n][k-perm] fp16
__device__ __align__(16) __half g_qh[HEADS*NTOK*HD];    // fp16, xQSCALE, k-permuted
__device__ __align__(16) __half g_kh[HEADS*NTOK*HD];    // fp16, k-permuted
__device__ __align__(16) __half g_vh[HEADS*NTOK*HD];    // fp16 V^T [h][c][m'], m-permuted
__device__ __align__(16) __half g_rp16[2*(2*G-1)*HD];   // fp16 rp x8, k-permuted
__device__ __align__(16) float  g_relh[HEADS*NTOK*G];   // x log2e (via g_qh scale)
__device__ __align__(16) float  g_relw[HEADS*NTOK*G];
__device__ __align__(16) __half g_aoh[NTOK*DIM];        // fp16 attn out, k-permuted

// ---------------- helpers ---------------------------------------------------
__device__ __forceinline__ void mma16(float* d,
                                      uint32_t a0, uint32_t a1, uint32_t a2, uint32_t a3,
                                      uint32_t b0, uint32_t b1) {
    asm volatile("mma.sync.aligned.m16n8k16.row.col.f32.f16.f16.f32 "
                 "{%0,%1,%2,%3},{%4,%5,%6,%7},{%8,%9},{%0,%1,%2,%3};"
                 : "+f"(d[0]), "+f"(d[1]), "+f"(d[2]), "+f"(d[3])
                 : "r"(a0), "r"(a1), "r"(a2), "r"(a3), "r"(b0), "r"(b1));
}
__device__ __forceinline__ uint32_t packh2(float lo, float hi) {
    __half2 h = __floats2half2_rn(lo, hi);
    return *(uint32_t*)&h;
}
__device__ __forceinline__ uint32_t h2exp2(uint32_t x) {
    uint32_t r;
    asm("ex2.approx.f16x2 %0, %1;" : "=r"(r) : "r"(x));
    return r;
}
__device__ __forceinline__ void cpa16(uint32_t dst, const void* src) {
    asm volatile("cp.async.cg.shared.global [%0], [%1], 16;" :: "r"(dst), "l"(src));
}
#define CP_COMMIT() asm volatile("cp.async.commit_group;")
#define CP_WAIT(n)  asm volatile("cp.async.wait_group " #n ";")
#define ONES2 0x3C003C00u

// within-16 k-permutation for m16n8k16 frags: logical k -> phys 4*tt + 2*hi + lo
__device__ __forceinline__ int permk(int k) {
    int r = k & 15;
    return (k & ~15) + 4 * ((r & 7) >> 1) + 2 * (r >> 3) + (k & 1);
}

// ---------------- kernel 0: x -> fp16 k-permuted, + rp tables ---------------
__global__ __launch_bounds__(256) void prep_xrp(const float* __restrict__ x,
                                                const float* __restrict__ rph,
                                                const float* __restrict__ rpw) {
    int gidx = blockIdx.x * 256 + threadIdx.x;
    const int NX4 = NTOK * DIM / 4;                  // 442368 float4 slots
    if (gidx < NX4) {
        int i = gidx * 4;
        float4 v = *(const float4*)(x + i);
        int p0 = permk(i);
        int p1 = permk(i + 2);
        *(__half2*)(g_xh + p0) = __floats2half2_rn(v.x, v.y);
        *(__half2*)(g_xh + p1) = __floats2half2_rn(v.z, v.w);
    } else {
        int id = gidx - NX4;                         // rp elements
        if (id >= 2 * (2*G-1) * HD) return;
        int z = id / ((2*G-1) * HD);
        int rem = id - z * (2*G-1) * HD;
        int row = rem / HD, k = rem - row * HD;
        const float* src = z ? rpw : rph;
        g_rp16[z * (2*G-1) * HD + row * HD + permk(k)] =
            __float2half_rn(src[row * HD + k] * 8.f);
    }
}

// ---------------- kernel 1: fuse LoRA + transpose -> fp16 k-permuted --------
__global__ __launch_bounds__(256) void fuse_wt(
    const float* __restrict__ Wq, const float* __restrict__ Aq, const float* __restrict__ Bq,
    const float* __restrict__ Wk, const float* __restrict__ Ak, const float* __restrict__ Bk,
    const float* __restrict__ Wv, const float* __restrict__ Av, const float* __restrict__ Bv,
    const float* __restrict__ Wp)
{
    __shared__ float tb[32][33];
    int z = blockIdx.z;
    const float *W, *A = nullptr, *B = nullptr;
    __half* O;
    if (z == 0)      { W = Wq; A = Aq; B = Bq; O = g_Wqkvh; }
    else if (z == 1) { W = Wk; A = Ak; B = Bk; O = g_Wqkvh + DIM*DIM; }
    else if (z == 2) { W = Wv; A = Av; B = Bv; O = g_Wqkvh + 2*DIM*DIM; }
    else             { W = Wp;                 O = g_Wph; }
    int kb = blockIdx.y * 32, nb = blockIdx.x * 32;
    int tx = threadIdx.x & 31, ty = threadIdx.x >> 5;
#pragma unroll
    for (int s = 0; s < 4; s++)
        tb[ty + 8 * s][tx] = W[(kb + ty + 8 * s) * DIM + nb + tx];
    __syncthreads();
#pragma unroll
    for (int s = 0; s < 4; s++) {
        int n = nb + ty + 8 * s;
        int k = kb + tx;
        float v = tb[tx][ty + 8 * s];
        if (z < 3) {
#pragma unroll
            for (int r = 0; r < RANK; r++)
                v += A[k * RANK + r] * B[r * DIM + n];
        }
        O[n * DIM + permk(k)] = __float2half_rn(v);
    }
}

// ---------------- fp16 GEMM core (templated warp grid) ---------------------
#define LDH 80
template<int WM, int WN, int NJ>
__device__ __forceinline__ void gemm16_body(const __half* __restrict__ Ain,
                                            const __half* __restrict__ Btn,
                                            float acc[2][NJ][4], __half* smh)
{
    const int MROWS = WM * 32;
    const int NROWS = WN * NJ * 8;
    const int BUFA = MROWS * LDH;
    const int BUFB = NROWS * LDH;
    int tid = threadIdx.x;
    int w = tid >> 5, l = tid & 31, g = l >> 2, t = l & 3;
    int wm = w / WN, wn = w % WN;
    __half* AS0 = smh;               __half* AS1 = AS0 + BUFA;
    __half* BS0 = AS1 + BUFA;        __half* BS1 = BS0 + BUFB;
    uint32_t as[2] = { (uint32_t)__cvta_generic_to_shared(AS0),
                       (uint32_t)__cvta_generic_to_shared(AS1) };
    uint32_t bs[2] = { (uint32_t)__cvta_generic_to_shared(BS0),
                       (uint32_t)__cvta_generic_to_shared(BS1) };

#pragma unroll
    for (int s = 0; s < MROWS / 32; s++) {
        int id = tid + s * 256;
        int r = id >> 3, ch = (id & 7) * 8;
        cpa16(as[0] + (r * LDH + ch) * 2, Ain + r * DIM + ch);
    }
#pragma unroll
    for (int s = 0; s < NROWS / 32; s++) {
        int id = tid + s * 256;
        int r = id >> 3, ch = (id & 7) * 8;
        cpa16(bs[0] + (r * LDH + ch) * 2, Btn + r * DIM + ch);
    }
    CP_COMMIT();

    for (int c = 0; c < 12; c++) {
        int buf = c & 1;
        if (c < 11) {
            int nb2 = buf ^ 1;
            int k0 = (c + 1) * 64;
#pragma unroll
            for (int s = 0; s < MROWS / 32; s++) {
                int id = tid + s * 256;
                int r = id >> 3, ch = (id & 7) * 8;
                cpa16(as[nb2] + (r * LDH + ch) * 2, Ain + r * DIM + k0 + ch);
            }
#pragma unroll
            for (int s = 0; s < NROWS / 32; s++) {
                int id = tid + s * 256;
                int r = id >> 3, ch = (id & 7) * 8;
                cpa16(bs[nb2] + (r * LDH + ch) * 2, Btn + r * DIM + k0 + ch);
            }
            CP_COMMIT();
            CP_WAIT(1);
        } else {
            CP_WAIT(0);
        }
        __syncthreads();
        const __half* As = buf ? AS1 : AS0;
        const __half* Bs = buf ? BS1 : BS0;
#pragma unroll
        for (int ks = 0; ks < 4; ks++) {
            int off = ks * 16 + 4 * t;
            uint32_t a[2][4];
#pragma unroll
            for (int i = 0; i < 2; i++) {
                int r = wm * 32 + i * 16;
                uint2 lo = *(const uint2*)&As[(r + g) * LDH + off];
                uint2 hi = *(const uint2*)&As[(r + g + 8) * LDH + off];
                a[i][0] = lo.x; a[i][1] = hi.x; a[i][2] = lo.y; a[i][3] = hi.y;
            }
#pragma unroll
            for (int j = 0; j < NJ; j++) {
                int n = wn * (NJ * 8) + j * 8;
                uint2 b = *(const uint2*)&Bs[(n + g) * LDH + off];
                mma16(acc[0][j], a[0][0], a[0][1], a[0][2], a[0][3], b.x, b.y);
                mma16(acc[1][j], a[1][0], a[1][1], a[1][2], a[1][3], b.x, b.y);
            }
        }
        __syncthreads();
    }
}

// ---------------- kernel 2: fused QKV GEMM (fp16, 128m x 64n) --------------
__global__ __launch_bounds__(256, 3) void gemm_qkvf(
    const float* __restrict__ bq, const float* __restrict__ bk, const float* __restrict__ bv)
{
    extern __shared__ __half smh[];
    int m0 = blockIdx.y * 128, n0 = blockIdx.x * 64;
    float acc[2][4][4];
#pragma unroll
    for (int i = 0; i < 2; i++)
#pragma unroll
        for (int j = 0; j < 4; j++)
#pragma unroll
            for (int e = 0; e < 4; e++) acc[i][j][e] = 0.f;
    gemm16_body<4, 2, 4>(g_xh + m0 * DIM, g_Wqkvh + n0 * DIM, acc, smh);

    int z = n0 / DIM;
    int nb = n0 - z * DIM;
    const float* bias = (z == 0) ? bq : (z == 1) ? bk : bv;
    int tid = threadIdx.x;
    int w = tid >> 5, l = tid & 31, g = l >> 2, t = l & 3;
    int wm = w >> 1, wn = w & 1;
#pragma unroll
    for (int i = 0; i < 2; i++) {
        int r0 = m0 + wm * 32 + i * 16 + g;
#pragma unroll
        for (int j = 0; j < 4; j++) {
            int c = nb + wn * 32 + j * 8 + t * 2;
            int h = c >> 6, cc = c & 63;
            float e0 = acc[i][j][0] + bias[c];
            float e1 = acc[i][j][1] + bias[c + 1];
            float e2 = acc[i][j][2] + bias[c];
            float e3 = acc[i][j][3] + bias[c + 1];
            if (z == 0) {
                int pcc = permk(cc);
                __half* qh = g_qh + h * (NTOK * HD);
                *(__half2*)&qh[r0 * HD + pcc]       = __floats2half2_rn(e0 * QSCALE, e1 * QSCALE);
                *(__half2*)&qh[(r0 + 8) * HD + pcc] = __floats2half2_rn(e2 * QSCALE, e3 * QSCALE);
            } else if (z == 1) {
                int pcc = permk(cc);
                __half* kh = g_kh + h * (NTOK * HD);
                *(__half2*)&kh[r0 * HD + pcc]       = __floats2half2_rn(e0, e1);
                *(__half2*)&kh[(r0 + 8) * HD + pcc] = __floats2half2_rn(e2, e3);
            } else {
                __half* vh = g_vh + h * (NTOK * HD);
                int pm0 = (r0 & ~15) + ((g >> 1) << 2) + (g & 1);
                int pm1 = pm0 + 2;
                vh[cc * NTOK + pm0]       = __float2half_rn(e0);
                vh[(cc + 1) * NTOK + pm0] = __float2half_rn(e1);
                vh[cc * NTOK + pm1]       = __float2half_rn(e2);
                vh[(cc + 1) * NTOK + pm1] = __float2half_rn(e3);
            }
        }
    }
}

// ---------------- kernel 5: output projection (fp16, 64m x 64n) -------------
__global__ __launch_bounds__(256, 3) void gemm_projf(
    const float* __restrict__ bp, float* __restrict__ out)
{
    extern __shared__ __half smh[];
    int m0 = blockIdx.y * 64, n0 = blockIdx.x * 64;
    float acc[2][2][4];
#pragma unroll
    for (int i = 0; i < 2; i++)
#pragma unroll
        for (int j = 0; j < 2; j++)
#pragma unroll
            for (int e = 0; e < 4; e++) acc[i][j][e] = 0.f;
    gemm16_body<2, 4, 2>(g_aoh + m0 * DIM, g_Wph + n0 * DIM, acc, smh);

    int tid = threadIdx.x;
    int w = tid >> 5, l = tid & 31, g = l >> 2, t = l & 3;
    int wm = w >> 2, wn = w & 3;
#pragma unroll
    for (int i = 0; i < 2; i++) {
        int r0 = m0 + wm * 32 + i * 16 + g;
#pragma unroll
        for (int j = 0; j < 2; j++) {
            int c = n0 + wn * 16 + j * 8 + t * 2;
            float2 v0 = make_float2(acc[i][j][0] + bp[c], acc[i][j][1] + bp[c + 1]);
            float2 v1 = make_float2(acc[i][j][2] + bp[c], acc[i][j][3] + bp[c + 1]);
            *(float2*)&out[r0 * DIM + c] = v0;
            *(float2*)&out[(r0 + 8) * DIM + c] = v1;
        }
    }
}

// ---------------- kernel 3: rel-pos tables, staging-free fp16 mma -----------
__global__ __launch_bounds__(192) void rel_mma_g()
{
    int head = blockIdx.x, p = blockIdx.y, z = blockIdx.z;
    int tid = threadIdx.x;
    int w = tid >> 5, l = tid & 31, g = l >> 2, t = l & 3;
    const __half* qhead = g_qh + head * (NTOK * HD);
    const __half* rpt = g_rp16 + z * (2*G-1) * HD;

    int brow = p + 47 - (w * 8 + g);
    uint2 bfr[4];
#pragma unroll
    for (int ks = 0; ks < 4; ks++)
        bfr[ks] = *(const uint2*)(rpt + brow * HD + 16 * ks + 4 * t);

    float acc[3][4];
#pragma unroll
    for (int i = 0; i < 3; i++)
#pragma unroll
        for (int e = 0; e < 4; e++) acc[i][e] = 0.f;

#pragma unroll
    for (int ks = 0; ks < 4; ks++) {
#pragma unroll
        for (int i = 0; i < 3; i++) {
            int rA = i * 16;
            int n0 = (z == 0) ? (p * G + rA + g)     : ((rA + g) * G + p);
            int n1 = (z == 0) ? (p * G + rA + g + 8) : ((rA + g + 8) * G + p);
            uint2 lo = *(const uint2*)(qhead + n0 * HD + 16 * ks + 4 * t);
            uint2 hi = *(const uint2*)(qhead + n1 * HD + 16 * ks + 4 * t);
            mma16(acc[i], lo.x, hi.x, lo.y, hi.y, bfr[ks].x, bfr[ks].y);
        }
    }

    float* dst = ((z == 0) ? g_relh : g_relw) + head * NTOK * G;
    int j = w * 8 + t * 2;
#pragma unroll
    for (int i = 0; i < 3; i++) {
        int r0 = i * 16 + g;
        int n0 = (z == 0) ? (p * G + r0)     : (r0 * G + p);
        int n1 = (z == 0) ? (p * G + r0 + 8) : ((r0 + 8) * G + p);
        *(float2*)&dst[n0 * G + j] = make_float2(acc[i][0], acc[i][1]);
        *(float2*)&dst[n1 * G + j] = make_float2(acc[i][2], acc[i][3]);
    }
}

// ---------------- kernel 4: fp16 flash 64q/128thr/4CTA, ex2 + ones-mma ------
#define LKH 80
#define LVH 80
__global__ __launch_bounds__(128, 4) void flash9()
{
    extern __shared__ __half smf[];
    __half* Kb[2] = { smf,             smf + 64 * LKH };
    __half* Vb[2] = { smf + 2*64*LKH,  smf + 2*64*LKH + 64 * LVH };
    uint32_t kba[2] = { (uint32_t)__cvta_generic_to_shared(Kb[0]),
                        (uint32_t)__cvta_generic_to_shared(Kb[1]) };
    uint32_t vba[2] = { (uint32_t)__cvta_generic_to_shared(Vb[0]),
                        (uint32_t)__cvta_generic_to_shared(Vb[1]) };

    int tile = blockIdx.x, head = blockIdx.y;
    int tid = threadIdx.x, w = tid >> 5, l = tid & 31, g = l >> 2, t = l & 3;
    const __half* qhb = g_qh + head * (NTOK * HD) + tile * 64 * HD;
    const __half* khb = g_kh + head * (NTOK * HD);
    const __half* vhb = g_vh + head * (NTOK * HD);

    int pr = w * 16;
    uint32_t qa[4][4];
#pragma unroll
    for (int ks = 0; ks < 4; ks++) {
        uint2 lo = *(const uint2*)(qhb + (pr + g) * HD + 16 * ks + 4 * t);
        uint2 hi = *(const uint2*)(qhb + (pr + g + 8) * HD + 16 * ks + 4 * t);
        qa[ks][0] = lo.x; qa[ks][1] = hi.x; qa[ks][2] = lo.y; qa[ks][3] = hi.y;
    }

    // issue K(0)+V(0): 512 16B chunks each, 128 threads x 4
#pragma unroll
    for (int s = 0; s < 4; s++) {
        int id = tid + s * 128;
        int r = id >> 3, ch = (id & 7) * 8;
        cpa16(kba[0] + (r * LKH + ch) * 2, khb + r * HD + ch);
        cpa16(vba[0] + (r * LVH + ch) * 2, vhb + r * NTOK + ch);
    }
    CP_COMMIT();

    int rg0 = tile * 64 + pr + g;
    const float* rhb = g_relh + head * NTOK * G;
    const float* rwb = g_relw + head * NTOK * G;

    float o[8][4];
#pragma unroll
    for (int j = 0; j < 8; j++)
#pragma unroll
        for (int e = 0; e < 4; e++) o[j][e] = 0.f;
    float ol[4] = {0.f, 0.f, 0.f, 0.f};

    for (int kt = 0; kt < NKT; kt++) {
        CP_WAIT(0);
        __syncthreads();

        if (kt + 1 < NKT) {
            int nb = (kt + 1) & 1;
            const __half* ksrc = khb + (kt + 1) * 64 * HD;
            const __half* vsrc = vhb + (kt + 1) * 64;
#pragma unroll
            for (int s = 0; s < 4; s++) {
                int id = tid + s * 128;
                int r = id >> 3, ch = (id & 7) * 8;
                cpa16(kba[nb] + (r * LKH + ch) * 2, ksrc + r * HD + ch);
                cpa16(vba[nb] + (r * LVH + ch) * 2, vsrc + r * NTOK + ch);
            }
            CP_COMMIT();
        }

        const __half* Ks = Kb[kt & 1];
        const __half* Vt = Vb[kt & 1];

        float s4[8][4];
#pragma unroll
        for (int j = 0; j < 8; j++)
#pragma unroll
            for (int e = 0; e < 4; e++) s4[j][e] = 0.f;
#pragma unroll
        for (int ks = 0; ks < 4; ks++) {
#pragma unroll
            for (int j = 0; j < 8; j++) {
                uint2 b = *(const uint2*)&Ks[(j * 8 + g) * LKH + 16 * ks + 4 * t];
                mma16(s4[j], qa[ks][0], qa[ks][1], qa[ks][2], qa[ks][3], b.x, b.y);
            }
        }

        int colbase = kt * 64;
        int khA = colbase / G;
        int khB = (colbase + 63) / G;
        float rhA0 = rhb[rg0 * G + khA],       rhB0 = rhb[rg0 * G + khB];
        float rhA1 = rhb[(rg0 + 8) * G + khA], rhB1 = rhb[(rg0 + 8) * G + khB];
        uint32_t pa[8][2];
#pragma unroll
        for (int j = 0; j < 8; j++) {
            int c0 = colbase + j * 8 + t * 2;
            int kh0 = c0 / G, kw0 = c0 - kh0 * G;
            float rh0 = (kh0 == khA) ? rhA0 : rhB0;
            float rh1 = (kh0 == khA) ? rhA1 : rhB1;
            float2 w0 = *(const float2*)&rwb[rg0 * G + kw0];
            float2 w1 = *(const float2*)&rwb[(rg0 + 8) * G + kw0];
            pa[j][0] = h2exp2(packh2(s4[j][0] + rh0 + w0.x, s4[j][1] + rh0 + w0.y));
            pa[j][1] = h2exp2(packh2(s4[j][2] + rh1 + w1.x, s4[j][3] + rh1 + w1.y));
        }

#pragma unroll
        for (int ms = 0; ms < 4; ms++) {
            uint32_t a0 = pa[2*ms][0],   a1 = pa[2*ms][1];
            uint32_t a2 = pa[2*ms+1][0], a3 = pa[2*ms+1][1];
            mma16(ol, a0, a1, a2, a3, ONES2, ONES2);
#pragma unroll
            for (int j = 0; j < 8; j++) {
                uint2 b = *(const uint2*)&Vt[(j * 8 + g) * LVH + 16 * ms + 4 * t];
                mma16(o[j], a0, a1, a2, a3, b.x, b.y);
            }
        }
    }

    float inv0 = 1.f / ol[0], inv1 = 1.f / ol[2];

    int nq0 = tile * 64 + pr + g;
#pragma unroll
    for (int j = 0; j < 8; j++) {
        int c = head * HD + j * 8 + t * 2;
        int pc = permk(c);
        *(__half2*)&g_aoh[nq0 * DIM + pc]       = __floats2half2_rn(o[j][0] * inv0, o[j][1] * inv0);
        *(__half2*)&g_aoh[(nq0 + 8) * DIM + pc] = __floats2half2_rn(o[j][2] * inv1, o[j][3] * inv1);
    }
}

// ---------------- launch ----------------------------------------------------
extern "C" void kernel_launch(void* const* d_in, const int* in_sizes, int n_in,
                              void* d_out, int out_size)
{
    const float* x   = (const float*)d_in[0];
    const float* Wq  = (const float*)d_in[1];
    const float* bq  = (const float*)d_in[2];
    const float* Wk  = (const float*)d_in[3];
    const float* bk  = (const float*)d_in[4];
    const float* Wv  = (const float*)d_in[5];
    const float* bv  = (const float*)d_in[6];
    const float* Wp  = (const float*)d_in[7];
    const float* bp  = (const float*)d_in[8];
    const float* rph = (const float*)d_in[9];
    const float* rpw = (const float*)d_in[10];
    const float* Aq  = (const float*)d_in[11];
    const float* Bq  = (const float*)d_in[12];
    const float* Ak  = (const float*)d_in[13];
    const float* Bk  = (const float*)d_in[14];
    const float* Av  = (const float*)d_in[15];
    const float* Bv  = (const float*)d_in[16];
    float* out = (float*)d_out;

    const int qkv_smem   = 2 * (128 + 64) * LDH * (int)sizeof(__half);           // 61440
    const int proj_smem  = 2 * (64 + 64) * LDH * (int)sizeof(__half);            // 40960
    const int flash_smem = (2 * 64 * LKH + 2 * 64 * LVH) * (int)sizeof(__half);  // 40960
    cudaFuncSetAttribute(gemm_qkvf, cudaFuncAttributeMaxDynamicSharedMemorySize, qkv_smem);
    cudaFuncSetAttribute(gemm_projf, cudaFuncAttributeMaxDynamicSharedMemorySize, proj_smem);
    cudaFuncSetAttribute(flash9, cudaFuncAttributeMaxDynamicSharedMemorySize, flash_smem);

    const int NX4 = NTOK * DIM / 4;
    const int prep_total = NX4 + 2 * (2*G-1) * HD;
    prep_xrp<<<(prep_total + 255) / 256, 256>>>(x, rph, rpw);
    fuse_wt<<<dim3(24, 24, 4), 256>>>(Wq, Aq, Bq, Wk, Ak, Bk, Wv, Av, Bv, Wp);
    gemm_qkvf<<<dim3(36, 18), 256, qkv_smem>>>(bq, bk, bv);
    rel_mma_g<<<dim3(HEADS, G, 2), 192>>>();
    flash9<<<dim3(NTOK / 64, HEADS), 128, flash_smem>>>();
    gemm_projf<<<dim3(12, 36), 256, proj_smem>>>(bp, out);
}

// round 17
// speedup vs baseline: 1.1742x; 1.0104x over previous
#include <cuda_runtime.h>
#include <cuda_fp16.h>
#include <cstdint>

#define DIM 768
#define HEADS 12
#define HD 64
#define G 48
#define NTOK 2304
#define RANK 8
#define NKT 36      // 2304/64 k-tiles
#define QSCALE (0.125f * 1.44269504f)   // 1/sqrt(64) * log2(e), folded into q

// ---------------- scratch --------------------------------------------------
__device__ __align__(16) __half g_xh[NTOK*DIM];         // fp16 x, k-permuted
__device__ __align__(16) __half g_Wqkvh[3*DIM*DIM];     // fused [n][k-perm] fp16
__device__ __align__(16) __half g_Wph[DIM*DIM];         // [n][k-perm] fp16
__device__ __align__(16) __half g_qh[HEADS*NTOK*HD];    // fp16, xQSCALE, k-permuted
__device__ __align__(16) __half g_kh[HEADS*NTOK*HD];    // fp16, k-permuted
__device__ __align__(16) __half g_vh[HEADS*NTOK*HD];    // fp16 V^T [h][c][m'], m-permuted
__device__ __align__(16) __half g_rp16[2*(2*G-1)*HD];   // fp16 rp x8, k-permuted
__device__ __align__(16) float  g_relh[HEADS*NTOK*G];   // x log2e (via g_qh scale)
__device__ __align__(16) float  g_relw[HEADS*NTOK*G];
__device__ __align__(16) __half g_aoh[NTOK*DIM];        // fp16 attn out, k-permuted

// ---------------- helpers ---------------------------------------------------
__device__ __forceinline__ void mma16(float* d,
                                      uint32_t a0, uint32_t a1, uint32_t a2, uint32_t a3,
                                      uint32_t b0, uint32_t b1) {
    asm volatile("mma.sync.aligned.m16n8k16.row.col.f32.f16.f16.f32 "
                 "{%0,%1,%2,%3},{%4,%5,%6,%7},{%8,%9},{%0,%1,%2,%3};"
                 : "+f"(d[0]), "+f"(d[1]), "+f"(d[2]), "+f"(d[3])
                 : "r"(a0), "r"(a1), "r"(a2), "r"(a3), "r"(b0), "r"(b1));
}
__device__ __forceinline__ uint32_t packh2(float lo, float hi) {
    __half2 h = __floats2half2_rn(lo, hi);
    return *(uint32_t*)&h;
}
__device__ __forceinline__ uint32_t h2exp2(uint32_t x) {
    uint32_t r;
    asm("ex2.approx.f16x2 %0, %1;" : "=r"(r) : "r"(x));
    return r;
}
__device__ __forceinline__ void cpa16(uint32_t dst, const void* src) {
    asm volatile("cp.async.cg.shared.global [%0], [%1], 16;" :: "r"(dst), "l"(src));
}
#define CP_COMMIT() asm volatile("cp.async.commit_group;")
#define CP_WAIT(n)  asm volatile("cp.async.wait_group " #n ";")
#define ONES2 0x3C003C00u

// within-16 k-permutation for m16n8k16 frags: logical k -> phys 4*tt + 2*hi + lo
__device__ __forceinline__ int permk(int k) {
    int r = k & 15;
    return (k & ~15) + 4 * ((r & 7) >> 1) + 2 * (r >> 3) + (k & 1);
}

// ---------------- kernel 0: x -> fp16 k-permuted, + rp tables ---------------
__global__ __launch_bounds__(256) void prep_xrp(const float* __restrict__ x,
                                                const float* __restrict__ rph,
                                                const float* __restrict__ rpw) {
    int gidx = blockIdx.x * 256 + threadIdx.x;
    const int NX4 = NTOK * DIM / 4;
    if (gidx < NX4) {
        int i = gidx * 4;
        float4 v = *(const float4*)(x + i);
        int p0 = permk(i);
        int p1 = permk(i + 2);
        *(__half2*)(g_xh + p0) = __floats2half2_rn(v.x, v.y);
        *(__half2*)(g_xh + p1) = __floats2half2_rn(v.z, v.w);
    } else {
        int id = gidx - NX4;
        if (id >= 2 * (2*G-1) * HD) return;
        int z = id / ((2*G-1) * HD);
        int rem = id - z * (2*G-1) * HD;
        int row = rem / HD, k = rem - row * HD;
        const float* src = z ? rpw : rph;
        g_rp16[z * (2*G-1) * HD + row * HD + permk(k)] =
            __float2half_rn(src[row * HD + k] * 8.f);
    }
}

// ---------------- kernel 1: fuse LoRA + transpose -> fp16 (half2 stores) ----
__global__ __launch_bounds__(256) void fuse_wt(
    const float* __restrict__ Wq, const float* __restrict__ Aq, const float* __restrict__ Bq,
    const float* __restrict__ Wk, const float* __restrict__ Ak, const float* __restrict__ Bk,
    const float* __restrict__ Wv, const float* __restrict__ Av, const float* __restrict__ Bv,
    const float* __restrict__ Wp)
{
    __shared__ float tb[32][33];           // tb[k][n]
    int z = blockIdx.z;
    const float *W, *A = nullptr, *B = nullptr;
    __half* O;
    if (z == 0)      { W = Wq; A = Aq; B = Bq; O = g_Wqkvh; }
    else if (z == 1) { W = Wk; A = Ak; B = Bk; O = g_Wqkvh + DIM*DIM; }
    else if (z == 2) { W = Wv; A = Av; B = Bv; O = g_Wqkvh + 2*DIM*DIM; }
    else             { W = Wp;                 O = g_Wph; }
    int kb = blockIdx.y * 32, nb = blockIdx.x * 32;
    int tx = threadIdx.x & 31, ty = threadIdx.x >> 5;
#pragma unroll
    for (int s = 0; s < 4; s++)
        tb[ty + 8 * s][tx] = W[(kb + ty + 8 * s) * DIM + nb + tx];
    __syncthreads();

    // store phase: thread owns k-pair (2*l16), n = nidx + 16*s
    int l16 = threadIdx.x & 15;
    int nidx = threadIdx.x >> 4;          // 0..15
    int kk = kb + l16 * 2;
    int pk = permk(kk & 63) + (kk & ~63); // permk acts within 16; keep full offset
#pragma unroll
    for (int s = 0; s < 2; s++) {
        int nloc = nidx + 16 * s;
        int n = nb + nloc;
        float v0 = tb[l16 * 2][nloc];
        float v1 = tb[l16 * 2 + 1][nloc];
        if (z < 3) {
#pragma unroll
            for (int r = 0; r < RANK; r++) {
                float br = B[r * DIM + n];
                v0 += A[kk * RANK + r] * br;
                v1 += A[(kk + 1) * RANK + r] * br;
            }
        }
        *(__half2*)&O[n * DIM + pk] = __floats2half2_rn(v0, v1);
    }
}

// ---------------- fp16 GEMM core (templated warp grid) ---------------------
#define LDH 80
template<int WM, int WN, int NJ>
__device__ __forceinline__ void gemm16_body(const __half* __restrict__ Ain,
                                            const __half* __restrict__ Btn,
                                            float acc[2][NJ][4], __half* smh)
{
    const int MROWS = WM * 32;
    const int NROWS = WN * NJ * 8;
    const int BUFA = MROWS * LDH;
    const int BUFB = NROWS * LDH;
    int tid = threadIdx.x;
    int w = tid >> 5, l = tid & 31, g = l >> 2, t = l & 3;
    int wm = w / WN, wn = w % WN;
    __half* AS0 = smh;               __half* AS1 = AS0 + BUFA;
    __half* BS0 = AS1 + BUFA;        __half* BS1 = BS0 + BUFB;
    uint32_t as[2] = { (uint32_t)__cvta_generic_to_shared(AS0),
                       (uint32_t)__cvta_generic_to_shared(AS1) };
    uint32_t bs[2] = { (uint32_t)__cvta_generic_to_shared(BS0),
                       (uint32_t)__cvta_generic_to_shared(BS1) };

#pragma unroll
    for (int s = 0; s < MROWS / 32; s++) {
        int id = tid + s * 256;
        int r = id >> 3, ch = (id & 7) * 8;
        cpa16(as[0] + (r * LDH + ch) * 2, Ain + r * DIM + ch);
    }
#pragma unroll
    for (int s = 0; s < NROWS / 32; s++) {
        int id = tid + s * 256;
        int r = id >> 3, ch = (id & 7) * 8;
        cpa16(bs[0] + (r * LDH + ch) * 2, Btn + r * DIM + ch);
    }
    CP_COMMIT();

    for (int c = 0; c < 12; c++) {
        int buf = c & 1;
        if (c < 11) {
            int nb2 = buf ^ 1;
            int k0 = (c + 1) * 64;
#pragma unroll
            for (int s = 0; s < MROWS / 32; s++) {
                int id = tid + s * 256;
                int r = id >> 3, ch = (id & 7) * 8;
                cpa16(as[nb2] + (r * LDH + ch) * 2, Ain + r * DIM + k0 + ch);
            }
#pragma unroll
            for (int s = 0; s < NROWS / 32; s++) {
                int id = tid + s * 256;
                int r = id >> 3, ch = (id & 7) * 8;
                cpa16(bs[nb2] + (r * LDH + ch) * 2, Btn + r * DIM + k0 + ch);
            }
            CP_COMMIT();
            CP_WAIT(1);
        } else {
            CP_WAIT(0);
        }
        __syncthreads();
        const __half* As = buf ? AS1 : AS0;
        const __half* Bs = buf ? BS1 : BS0;
#pragma unroll
        for (int ks = 0; ks < 4; ks++) {
            int off = ks * 16 + 4 * t;
            uint32_t a[2][4];
#pragma unroll
            for (int i = 0; i < 2; i++) {
                int r = wm * 32 + i * 16;
                uint2 lo = *(const uint2*)&As[(r + g) * LDH + off];
                uint2 hi = *(const uint2*)&As[(r + g + 8) * LDH + off];
                a[i][0] = lo.x; a[i][1] = hi.x; a[i][2] = lo.y; a[i][3] = hi.y;
            }
#pragma unroll
            for (int j = 0; j < NJ; j++) {
                int n = wn * (NJ * 8) + j * 8;
                uint2 b = *(const uint2*)&Bs[(n + g) * LDH + off];
                mma16(acc[0][j], a[0][0], a[0][1], a[0][2], a[0][3], b.x, b.y);
                mma16(acc[1][j], a[1][0], a[1][1], a[1][2], a[1][3], b.x, b.y);
            }
        }
        __syncthreads();
    }
}

// ---------------- kernel 2: fused QKV GEMM (fp16, 128m x 64n) --------------
__global__ __launch_bounds__(256, 3) void gemm_qkvf(
    const float* __restrict__ bq, const float* __restrict__ bk, const float* __restrict__ bv)
{
    extern __shared__ __half smh[];
    int m0 = blockIdx.y * 128, n0 = blockIdx.x * 64;
    float acc[2][4][4];
#pragma unroll
    for (int i = 0; i < 2; i++)
#pragma unroll
        for (int j = 0; j < 4; j++)
#pragma unroll
            for (int e = 0; e < 4; e++) acc[i][j][e] = 0.f;
    gemm16_body<4, 2, 4>(g_xh + m0 * DIM, g_Wqkvh + n0 * DIM, acc, smh);

    int z = n0 / DIM;
    int nb = n0 - z * DIM;
    const float* bias = (z == 0) ? bq : (z == 1) ? bk : bv;
    int tid = threadIdx.x;
    int w = tid >> 5, l = tid & 31, g = l >> 2, t = l & 3;
    int wm = w >> 1, wn = w & 1;
#pragma unroll
    for (int i = 0; i < 2; i++) {
        int r0 = m0 + wm * 32 + i * 16 + g;
#pragma unroll
        for (int j = 0; j < 4; j++) {
            int c = nb + wn * 32 + j * 8 + t * 2;
            int h = c >> 6, cc = c & 63;
            float e0 = acc[i][j][0] + bias[c];
            float e1 = acc[i][j][1] + bias[c + 1];
            float e2 = acc[i][j][2] + bias[c];
            float e3 = acc[i][j][3] + bias[c + 1];
            if (z == 0) {
                int pcc = permk(cc);
                __half* qh = g_qh + h * (NTOK * HD);
                *(__half2*)&qh[r0 * HD + pcc]       = __floats2half2_rn(e0 * QSCALE, e1 * QSCALE);
                *(__half2*)&qh[(r0 + 8) * HD + pcc] = __floats2half2_rn(e2 * QSCALE, e3 * QSCALE);
            } else if (z == 1) {
                int pcc = permk(cc);
                __half* kh = g_kh + h * (NTOK * HD);
                *(__half2*)&kh[r0 * HD + pcc]       = __floats2half2_rn(e0, e1);
                *(__half2*)&kh[(r0 + 8) * HD + pcc] = __floats2half2_rn(e2, e3);
            } else {
                __half* vh = g_vh + h * (NTOK * HD);
                int pm0 = (r0 & ~15) + ((g >> 1) << 2) + (g & 1);
                int pm1 = pm0 + 2;
                vh[cc * NTOK + pm0]       = __float2half_rn(e0);
                vh[(cc + 1) * NTOK + pm0] = __float2half_rn(e1);
                vh[cc * NTOK + pm1]       = __float2half_rn(e2);
                vh[(cc + 1) * NTOK + pm1] = __float2half_rn(e3);
            }
        }
    }
}

// ---------------- kernel 5: output projection (fp16, 64m x 64n) -------------
__global__ __launch_bounds__(256, 3) void gemm_projf(
    const float* __restrict__ bp, float* __restrict__ out)
{
    extern __shared__ __half smh[];
    int m0 = blockIdx.y * 64, n0 = blockIdx.x * 64;
    float acc[2][2][4];
#pragma unroll
    for (int i = 0; i < 2; i++)
#pragma unroll
        for (int j = 0; j < 2; j++)
#pragma unroll
            for (int e = 0; e < 4; e++) acc[i][j][e] = 0.f;
    gemm16_body<2, 4, 2>(g_aoh + m0 * DIM, g_Wph + n0 * DIM, acc, smh);

    int tid = threadIdx.x;
    int w = tid >> 5, l = tid & 31, g = l >> 2, t = l & 3;
    int wm = w >> 2, wn = w & 3;
#pragma unroll
    for (int i = 0; i < 2; i++) {
        int r0 = m0 + wm * 32 + i * 16 + g;
#pragma unroll
        for (int j = 0; j < 2; j++) {
            int c = n0 + wn * 16 + j * 8 + t * 2;
            float2 v0 = make_float2(acc[i][j][0] + bp[c], acc[i][j][1] + bp[c + 1]);
            float2 v1 = make_float2(acc[i][j][2] + bp[c], acc[i][j][3] + bp[c + 1]);
            *(float2*)&out[r0 * DIM + c] = v0;
            *(float2*)&out[(r0 + 8) * DIM + c] = v1;
        }
    }
}

// ---------------- kernel 3: rel-pos tables, prefetched fragments ------------
__global__ __launch_bounds__(192) void rel_mma_g()
{
    int head = blockIdx.x, p = blockIdx.y, z = blockIdx.z;
    int tid = threadIdx.x;
    int w = tid >> 5, l = tid & 31, g = l >> 2, t = l & 3;
    const __half* qhead = g_qh + head * (NTOK * HD);
    const __half* rpt = g_rp16 + z * (2*G-1) * HD;

    // prefetch ALL fragments (max MLP, hide global latency)
    int brow = p + 47 - (w * 8 + g);
    uint2 bfr[4];
#pragma unroll
    for (int ks = 0; ks < 4; ks++)
        bfr[ks] = *(const uint2*)(rpt + brow * HD + 16 * ks + 4 * t);

    int rowA[3], rowB[3];
#pragma unroll
    for (int i = 0; i < 3; i++) {
        int rA = i * 16;
        rowA[i] = (z == 0) ? (p * G + rA + g)     : ((rA + g) * G + p);
        rowB[i] = (z == 0) ? (p * G + rA + g + 8) : ((rA + g + 8) * G + p);
    }
    uint2 alo[3][4], ahi[3][4];
#pragma unroll
    for (int i = 0; i < 3; i++)
#pragma unroll
        for (int ks = 0; ks < 4; ks++) {
            alo[i][ks] = *(const uint2*)(qhead + rowA[i] * HD + 16 * ks + 4 * t);
            ahi[i][ks] = *(const uint2*)(qhead + rowB[i] * HD + 16 * ks + 4 * t);
        }

    float acc[3][4];
#pragma unroll
    for (int i = 0; i < 3; i++)
#pragma unroll
        for (int e = 0; e < 4; e++) acc[i][e] = 0.f;

#pragma unroll
    for (int ks = 0; ks < 4; ks++)
#pragma unroll
        for (int i = 0; i < 3; i++)
            mma16(acc[i], alo[i][ks].x, ahi[i][ks].x, alo[i][ks].y, ahi[i][ks].y,
                  bfr[ks].x, bfr[ks].y);

    float* dst = ((z == 0) ? g_relh : g_relw) + head * NTOK * G;
    int j = w * 8 + t * 2;
#pragma unroll
    for (int i = 0; i < 3; i++) {
        int r0 = i * 16 + g;
        int n0 = (z == 0) ? (p * G + r0)     : (r0 * G + p);
        int n1 = (z == 0) ? (p * G + r0 + 8) : ((r0 + 8) * G + p);
        *(float2*)&dst[n0 * G + j] = make_float2(acc[i][0], acc[i][1]);
        *(float2*)&dst[n1 * G + j] = make_float2(acc[i][2], acc[i][3]);
    }
}

// ---------------- kernel 4: fp16 flash 64q/128thr/4CTA, ex2 + ones-mma ------
#define LKH 80
#define LVH 80
__global__ __launch_bounds__(128, 4) void flash9()
{
    extern __shared__ __half smf[];
    __half* Kb[2] = { smf,             smf + 64 * LKH };
    __half* Vb[2] = { smf + 2*64*LKH,  smf + 2*64*LKH + 64 * LVH };
    uint32_t kba[2] = { (uint32_t)__cvta_generic_to_shared(Kb[0]),
                        (uint32_t)__cvta_generic_to_shared(Kb[1]) };
    uint32_t vba[2] = { (uint32_t)__cvta_generic_to_shared(Vb[0]),
                        (uint32_t)__cvta_generic_to_shared(Vb[1]) };

    int tile = blockIdx.x, head = blockIdx.y;
    int tid = threadIdx.x, w = tid >> 5, l = tid & 31, g = l >> 2, t = l & 3;
    const __half* qhb = g_qh + head * (NTOK * HD) + tile * 64 * HD;
    const __half* khb = g_kh + head * (NTOK * HD);
    const __half* vhb = g_vh + head * (NTOK * HD);

    int pr = w * 16;
    uint32_t qa[4][4];
#pragma unroll
    for (int ks = 0; ks < 4; ks++) {
        uint2 lo = *(const uint2*)(qhb + (pr + g) * HD + 16 * ks + 4 * t);
        uint2 hi = *(const uint2*)(qhb + (pr + g + 8) * HD + 16 * ks + 4 * t);
        qa[ks][0] = lo.x; qa[ks][1] = hi.x; qa[ks][2] = lo.y; qa[ks][3] = hi.y;
    }

#pragma unroll
    for (int s = 0; s < 4; s++) {
        int id = tid + s * 128;
        int r = id >> 3, ch = (id & 7) * 8;
        cpa16(kba[0] + (r * LKH + ch) * 2, khb + r * HD + ch);
        cpa16(vba[0] + (r * LVH + ch) * 2, vhb + r * NTOK + ch);
    }
    CP_COMMIT();

    int rg0 = tile * 64 + pr + g;
    const float* rhb = g_relh + head * NTOK * G;
    const float* rwb = g_relw + head * NTOK * G;

    float o[8][4];
#pragma unroll
    for (int j = 0; j < 8; j++)
#pragma unroll
        for (int e = 0; e < 4; e++) o[j][e] = 0.f;
    float ol[4] = {0.f, 0.f, 0.f, 0.f};

    for (int kt = 0; kt < NKT; kt++) {
        CP_WAIT(0);
        __syncthreads();

        if (kt + 1 < NKT) {
            int nb = (kt + 1) & 1;
            const __half* ksrc = khb + (kt + 1) * 64 * HD;
            const __half* vsrc = vhb + (kt + 1) * 64;
#pragma unroll
            for (int s = 0; s < 4; s++) {
                int id = tid + s * 128;
                int r = id >> 3, ch = (id & 7) * 8;
                cpa16(kba[nb] + (r * LKH + ch) * 2, ksrc + r * HD + ch);
                cpa16(vba[nb] + (r * LVH + ch) * 2, vsrc + r * NTOK + ch);
            }
            CP_COMMIT();
        }

        const __half* Ks = Kb[kt & 1];
        const __half* Vt = Vb[kt & 1];

        float s4[8][4];
#pragma unroll
        for (int j = 0; j < 8; j++)
#pragma unroll
            for (int e = 0; e < 4; e++) s4[j][e] = 0.f;
#pragma unroll
        for (int ks = 0; ks < 4; ks++) {
#pragma unroll
            for (int j = 0; j < 8; j++) {
                uint2 b = *(const uint2*)&Ks[(j * 8 + g) * LKH + 16 * ks + 4 * t];
                mma16(s4[j], qa[ks][0], qa[ks][1], qa[ks][2], qa[ks][3], b.x, b.y);
            }
        }

        int colbase = kt * 64;
        int khA = colbase / G;
        int khB = (colbase + 63) / G;
        float rhA0 = rhb[rg0 * G + khA],       rhB0 = rhb[rg0 * G + khB];
        float rhA1 = rhb[(rg0 + 8) * G + khA], rhB1 = rhb[(rg0 + 8) * G + khB];
        uint32_t pa[8][2];
#pragma unroll
        for (int j = 0; j < 8; j++) {
            int c0 = colbase + j * 8 + t * 2;
            int kh0 = c0 / G, kw0 = c0 - kh0 * G;
            float rh0 = (kh0 == khA) ? rhA0 : rhB0;
            float rh1 = (kh0 == khA) ? rhA1 : rhB1;
            float2 w0 = *(const float2*)&rwb[rg0 * G + kw0];
            float2 w1 = *(const float2*)&rwb[(rg0 + 8) * G + kw0];
            pa[j][0] = h2exp2(packh2(s4[j][0] + rh0 + w0.x, s4[j][1] + rh0 + w0.y));
            pa[j][1] = h2exp2(packh2(s4[j][2] + rh1 + w1.x, s4[j][3] + rh1 + w1.y));
        }

#pragma unroll
        for (int ms = 0; ms < 4; ms++) {
            uint32_t a0 = pa[2*ms][0],   a1 = pa[2*ms][1];
            uint32_t a2 = pa[2*ms+1][0], a3 = pa[2*ms+1][1];
            mma16(ol, a0, a1, a2, a3, ONES2, ONES2);
#pragma unroll
            for (int j = 0; j < 8; j++) {
                uint2 b = *(const uint2*)&Vt[(j * 8 + g) * LVH + 16 * ms + 4 * t];
                mma16(o[j], a0, a1, a2, a3, b.x, b.y);
            }
        }
    }

    float inv0 = 1.f / ol[0], inv1 = 1.f / ol[2];

    int nq0 = tile * 64 + pr + g;
#pragma unroll
    for (int j = 0; j < 8; j++) {
        int c = head * HD + j * 8 + t * 2;
        int pc = permk(c);
        *(__half2*)&g_aoh[nq0 * DIM + pc]       = __floats2half2_rn(o[j][0] * inv0, o[j][1] * inv0);
        *(__half2*)&g_aoh[(nq0 + 8) * DIM + pc] = __floats2half2_rn(o[j][2] * inv1, o[j][3] * inv1);
    }
}

// ---------------- launch ----------------------------------------------------
extern "C" void kernel_launch(void* const* d_in, const int* in_sizes, int n_in,
                              void* d_out, int out_size)
{
    const float* x   = (const float*)d_in[0];
    const float* Wq  = (const float*)d_in[1];
    const float* bq  = (const float*)d_in[2];
    const float* Wk  = (const float*)d_in[3];
    const float* bk  = (const float*)d_in[4];
    const float* Wv  = (const float*)d_in[5];
    const float* bv  = (const float*)d_in[6];
    const float* Wp  = (const float*)d_in[7];
    const float* bp  = (const float*)d_in[8];
    const float* rph = (const float*)d_in[9];
    const float* rpw = (const float*)d_in[10];
    const float* Aq  = (const float*)d_in[11];
    const float* Bq  = (const float*)d_in[12];
    const float* Ak  = (const float*)d_in[13];
    const float* Bk  = (const float*)d_in[14];
    const float* Av  = (const float*)d_in[15];
    const float* Bv  = (const float*)d_in[16];
    float* out = (float*)d_out;

    const int qkv_smem   = 2 * (128 + 64) * LDH * (int)sizeof(__half);
    const int proj_smem  = 2 * (64 + 64) * LDH * (int)sizeof(__half);
    const int flash_smem = (2 * 64 * LKH + 2 * 64 * LVH) * (int)sizeof(__half);
    cudaFuncSetAttribute(gemm_qkvf, cudaFuncAttributeMaxDynamicSharedMemorySize, qkv_smem);
    cudaFuncSetAttribute(gemm_projf, cudaFuncAttributeMaxDynamicSharedMemorySize, proj_smem);
    cudaFuncSetAttribute(flash9, cudaFuncAttributeMaxDynamicSharedMemorySize, flash_smem);

    const int NX4 = NTOK * DIM / 4;
    const int prep_total = NX4 + 2 * (2*G-1) * HD;
    prep_xrp<<<(prep_total + 255) / 256, 256>>>(x, rph, rpw);
    fuse_wt<<<dim3(24, 24, 4), 256>>>(Wq, Aq, Bq, Wk, Ak, Bk, Wv, Av, Bv, Wp);
    gemm_qkvf<<<dim3(36, 18), 256, qkv_smem>>>(bq, bk, bv);
    rel_mma_g<<<dim3(HEADS, G, 2), 192>>>();
    flash9<<<dim3(NTOK / 64, HEADS), 128, flash_smem>>>();
    gemm_projf<<<dim3(12, 36), 256, proj_smem>>>(bp, out);
}